// round 1
// baseline (speedup 1.0000x reference)
#include <cuda_runtime.h>
#include <math.h>

// ---------------- problem constants ----------------
constexpr int NB   = 256;    // batch
constexpr int NA   = 285;    // angles
constexpr int ND   = 183;    // detectors
constexpr int NI   = 128;    // image N
constexpr int QS   = 184;    // padded q row stride (16B-aligned rows)

constexpr double RHO_D    = 1.4142135623730951 * 20.0;   // sqrt(2)*20
constexpr double DC_D     = 2.0 * RHO_D / 183.0;
constexpr double INVDC_D  = 1.0 / DC_D;
constexpr double H0_D     = 1.0 / (4.0 * DC_D * DC_D);
constexpr double SCALEQ_D = 12.0 * DC_D;                 // x*12 and q*DC folded
constexpr double PI_D     = 3.141592653589793;

// filtered sinogram scratch: 72960 rows x 184 floats = 53.7 MB (static, no alloc)
__device__ float g_q[(size_t)NB * NA * QS];

// ================= Stage 1: ramp-filter as banded conv =================
// q[row, n] = SCALEQ * ( h0*x[n] + sum_{odd o} g(o) * x[n-o] )
// block = 192 threads = 4 rows x 48 threads, 4 consecutive outputs/thread
__global__ __launch_bounds__(192) void filter_kernel(const float* __restrict__ x,
                                                     float* __restrict__ q) {
    __shared__ float xs[4 * 200];   // stride 200: rows offset by 8 banks
    __shared__ float G[384];        // g(o) at index o+182, zero-padded tail

    const int t = threadIdx.x;
    const int row0 = blockIdx.x * 4;

    // build g table (double-precision derivation, fp32 store)
    for (int i = t; i < 384; i += 192) {
        int o = i - 182;
        float v = 0.0f;
        if (o == 0) v = (float)H0_D;
        else if (o & 1) {
            double d = PI_D * (double)o * DC_D;
            v = (float)(-1.0 / (d * d));
        }
        G[i] = v;
    }
    // load 4 rows of x, zero-pad to 200
    {
        const float* xb = x + (size_t)row0 * ND;
        #pragma unroll
        for (int r = 0; r < 4; r++) {
            xs[r * 200 + t] = (t < ND) ? xb[r * ND + t] : 0.0f;
            int m2 = t + 192;
            if (m2 < 200) xs[r * 200 + m2] = 0.0f;
        }
    }
    __syncthreads();

    const int r  = t & 3;
    const int n0 = (t >> 2) * 4;          // 0,4,...,188 (n0>=184 unused)
    const float* xr = xs + r * 200;
    const float* Gp = G + n0 + 182;

    float a0 = 0.f, a1 = 0.f, a2 = 0.f, a3 = 0.f;

    // odd m -> even outputs n0, n0+2
    #pragma unroll 7
    for (int m = 1; m < ND; m += 2) {
        float xv = xr[m];
        a0 = fmaf(xv, Gp[0 - m], a0);
        a2 = fmaf(xv, Gp[2 - m], a2);
    }
    // even m -> odd outputs n0+1, n0+3
    #pragma unroll 4
    for (int m = 0; m < ND; m += 2) {
        float xv = xr[m];
        a1 = fmaf(xv, Gp[1 - m], a1);
        a3 = fmaf(xv, Gp[3 - m], a3);
    }
    // center tap (o = 0)
    const float h0 = (float)H0_D;
    a0 = fmaf(h0, xr[n0 + 0], a0);
    a1 = fmaf(h0, xr[n0 + 1], a1);
    a2 = fmaf(h0, xr[n0 + 2], a2);
    a3 = fmaf(h0, xr[n0 + 3], a3);

    const float sc = (float)SCALEQ_D;
    float* qr = q + (size_t)(row0 + r) * QS;
    if (n0 + 0 < ND) qr[n0 + 0] = a0 * sc;
    if (n0 + 1 < ND) qr[n0 + 1] = a1 * sc;
    if (n0 + 2 < ND) qr[n0 + 2] = a2 * sc;
    if (n0 + 3 < ND) qr[n0 + 3] = a3 * sc;
}

// ================= Stage 2: backprojection =================
// One block: 4 images (same b-group) x 8 image rows x 128 cols.
// 256 threads: j = t&127, 4 consecutive i per thread, 4 images -> 16 accums.
// k0/w computed ONCE per (pixel, angle), reused across the 4 images.
__device__ __forceinline__ void cp_async4(void* dst, const void* src) {
    unsigned s = (unsigned)__cvta_generic_to_shared(dst);
    asm volatile("cp.async.ca.shared.global [%0], [%1], 4;" :: "r"(s), "l"(src));
}
__device__ __forceinline__ void cp_async_commit() {
    asm volatile("cp.async.commit_group;");
}
__device__ __forceinline__ void cp_async_wait_all() {
    asm volatile("cp.async.wait_group 0;");
}

__global__ __launch_bounds__(256) void backproj_kernel(const float* __restrict__ q,
                                                       float* __restrict__ out) {
    __shared__ float  qb[2][4 * QS];   // double-buffered 4 rows
    __shared__ float2 csn[NA];         // (cos, sin) * invDC per angle

    const int t   = threadIdx.x;
    const int seg = blockIdx.x;        // 0..15 -> image rows [seg*8, seg*8+8)
    const int bg  = blockIdx.y;        // 0..63 -> images [bg*4, bg*4+4)

    // per-angle trig (double for exactness vs numpy)
    for (int idx = t; idx < NA; idx += 256) {
        double th = ((double)idx + 0.5) * (PI_D / (double)NA);
        double s, c;
        sincos(th, &s, &c);
        csn[idx] = make_float2((float)(c * INVDC_D), (float)(s * INVDC_D));
    }

    const int j  = t & 127;
    const int i0 = seg * 8 + (t >> 7) * 4;
    const float Yj = -20.0f + ((float)j  + 0.5f) * 0.3125f;
    const float Xi = -20.0f + ((float)i0 + 0.5f) * 0.3125f;

    const float* qbase = q + (size_t)(bg * 4) * NA * QS;

    // prologue: load angle-0 rows for the 4 images
    if (t < ND) {
        #pragma unroll
        for (int v = 0; v < 4; v++)
            qb[0][v * QS + t] = qbase[(size_t)v * NA * QS + t];
    }
    __syncthreads();

    float acc[4][4];
    #pragma unroll
    for (int v = 0; v < 4; v++)
        #pragma unroll
        for (int ii = 0; ii < 4; ii++) acc[v][ii] = 0.0f;

    int cur = 0;
    for (int a = 0; a < NA; a++) {
        const bool pf = (a + 1 < NA);
        const int nxt = cur ^ 1;
        // async prefetch of next angle's 4 rows into the other buffer
        if (pf && t < ND) {
            #pragma unroll
            for (int v = 0; v < 4; v++)
                cp_async4(&qb[nxt][v * QS + t],
                          &qbase[(size_t)v * NA * QS + (size_t)(a + 1) * QS + t]);
        }
        cp_async_commit();

        const float2 cs  = csn[a];
        const float  kf0 = fmaf(cs.x, Xi, fmaf(cs.y, Yj, 91.0f)); // RHO/DC-0.5 == 91
        const float  dk  = cs.x * 0.3125f;
        const float* qc  = qb[cur];

        #pragma unroll
        for (int ii = 0; ii < 4; ii++) {
            float kf = fmaf((float)ii, dk, kf0);
            kf = fminf(fmaxf(kf, 0.0f), 182.0f);
            int k0 = (int)kf;            // kf >= 0 -> trunc == floor
            k0 = min(k0, 181);
            float w = kf - (float)k0;
            const float* p = qc + k0;
            #pragma unroll
            for (int v = 0; v < 4; v++) {
                float g0 = p[v * QS];
                float g1 = p[v * QS + 1];
                acc[v][ii] = fmaf(w, g1 - g0, acc[v][ii] + g0);
            }
        }

        if (pf) {
            cp_async_wait_all();
            __syncthreads();
            cur = nxt;
        }
    }

    const float sc = (float)(PI_D / (double)NA);
    #pragma unroll
    for (int v = 0; v < 4; v++) {
        #pragma unroll
        for (int ii = 0; ii < 4; ii++) {
            out[(size_t)(bg * 4 + v) * (NI * NI) + (size_t)(i0 + ii) * NI + j] =
                acc[v][ii] * sc;
        }
    }
}

// ================= launch =================
extern "C" void kernel_launch(void* const* d_in, const int* in_sizes, int n_in,
                              void* d_out, int out_size) {
    (void)in_sizes; (void)n_in; (void)out_size;
    const float* x = (const float*)d_in[0];
    float* out = (float*)d_out;

    float* qptr = nullptr;
    cudaGetSymbolAddress((void**)&qptr, g_q);   // no allocation, just address

    filter_kernel<<<(NB * NA) / 4, 192>>>(x, qptr);
    backproj_kernel<<<dim3(16, 64), 256>>>(qptr, out);
}

// round 2
// speedup vs baseline: 1.2140x; 1.2140x over previous
#include <cuda_runtime.h>
#include <cuda_fp16.h>
#include <math.h>

// ---------------- problem constants ----------------
constexpr int NB = 256;    // batch
constexpr int NA = 285;    // angles
constexpr int ND = 183;    // detectors
constexpr int NI = 128;    // image N
constexpr int QQ = 184;    // quads per row (stride)

constexpr double RHO_D    = 1.4142135623730951 * 20.0;
constexpr double DC_D     = 2.0 * RHO_D / 183.0;
constexpr double INVDC_D  = 1.0 / DC_D;
constexpr double H0_D     = 1.0 / (4.0 * DC_D * DC_D);
constexpr double SCALEQ_D = 12.0 * DC_D;
constexpr double PI_D     = 3.141592653589793;

// filtered sinogram, fp16 interleaved-pair quads:
// Q[pair][a][k] = halfs (q_b0[k], q_b1[k], q_b0[k+1], q_b1[k+1])  (8 bytes)
// 128 pairs * 285 * 184 * 8B = 53.7 MB static scratch
__device__ uint2 g_q[(size_t)(NB / 2) * NA * QQ];

// ================= Stage 1: ramp filter (banded conv) =================
// Block: 2 images (b0,b0+1) x 2 angles (a0,a0+1); 192 threads = 4 rows x 48.
// Compact odd-tap table -> float2 loads; outputs staged to fp16 quads.
__global__ __launch_bounds__(192) void filter_kernel(const float* __restrict__ x,
                                                     uint2* __restrict__ Q) {
    __shared__ float   xs[4 * 200];      // 4 rows, zero-padded, stride 200
    __shared__ float   Godd[200];        // g(2i-181), zero beyond |o|>181
    __shared__ float2  G2[192];          // (Godd[i], Godd[i+1])
    __shared__ __half  st[2 * QQ * 2];   // [va][n][vb]

    const int t  = threadIdx.x;
    const int ap = blockIdx.x;           // angle pair
    const int p  = blockIdx.y;           // image pair
    const int a0 = 2 * ap, b0 = 2 * p;

    // odd-tap table (o = 2t-181 is always odd)
    if (t < 200) {
        int o = 2 * t - 181;
        float v = 0.0f;
        if (o >= -181 && o <= 181) {
            double d = PI_D * (double)o * DC_D;
            v = (float)(-1.0 / (d * d));
        }
        Godd[t] = v;
    }

    const int lr = t & 3;
    const int vb = lr & 1;
    const int va = lr >> 1;

    // load 4 input rows (rows indexed by (vb,va)), zero-padded
    #pragma unroll
    for (int r = 0; r < 4; r++) {
        int rvb = r & 1, rva = r >> 1;
        int aa = a0 + rva;
        const float* xr = x + ((size_t)(b0 + rvb) * NA + aa) * ND;
        xs[r * 200 + t] = (t < ND && aa < NA) ? xr[t] : 0.0f;
        if (t < 8) xs[r * 200 + 192 + t] = 0.0f;
    }
    __syncthreads();
    if (t < 192) G2[t] = make_float2(Godd[t], Godd[t + 1]);
    __syncthreads();

    const int n0 = (t >> 2) * 4;                  // 0..188
    const float*  xr = xs + lr * 200;
    const float2* g2 = G2   + (n0 >> 1) + 90;     // g2[-s] = G2[ie]
    const float*  gs = Godd + (n0 >> 1) + 92;     // gs[-s] = Godd[ie+2]

    float c0 = 0.f, c1 = 0.f, c2 = 0.f, c3 = 0.f;

    #pragma unroll 7
    for (int s = 0; s < 91; s++) {
        float2 xv = *(const float2*)(xr + 2 * s);   // (x[2s], x[2s+1])
        float2 ge = g2[-s];
        float  g3 = gs[-s];
        c0 = fmaf(xv.y, ge.x, c0);   // even outs use odd m = 2s+1
        c2 = fmaf(xv.y, ge.y, c2);
        c1 = fmaf(xv.x, ge.y, c1);   // odd outs use even m = 2s
        c3 = fmaf(xv.x, g3,   c3);
    }
    { // epilogue m = 182 (even) -> odd outputs only
        float  xe = xr[182];
        float2 gg = G2[n0 >> 1];
        c1 = fmaf(xe, gg.x, c1);
        c3 = fmaf(xe, gg.y, c3);
    }
    { // center tap
        const float h0 = (float)H0_D;
        c0 = fmaf(h0, xr[n0 + 0], c0);
        c1 = fmaf(h0, xr[n0 + 1], c1);
        c2 = fmaf(h0, xr[n0 + 2], c2);
        c3 = fmaf(h0, xr[n0 + 3], c3);
    }

    // stage as fp16:  st half index = (va*QQ + n)*2 + vb
    const float sc = (float)SCALEQ_D;
    if (n0 + 3 < QQ) {
        int base = (va * QQ + n0) * 2 + vb;
        st[base + 0] = __float2half_rn(c0 * sc);
        st[base + 2] = __float2half_rn(c1 * sc);
        st[base + 4] = __float2half_rn(c2 * sc);
        st[base + 6] = __float2half_rn(c3 * sc);
    }
    __syncthreads();

    // write quads: quad k = 8 bytes at half index (va*QQ+k)*2 .. +3
    const unsigned* sp = (const unsigned*)st;
    for (int u = t; u < 2 * ND; u += 192) {
        int qva = (u >= ND) ? 1 : 0;
        int k   = u - qva * ND;
        int aa  = a0 + qva;
        if (aa < NA) {
            int fi = qva * QQ + k;   // 32-bit word index
            uint2 qd = make_uint2(sp[fi], sp[fi + 1]);
            Q[((size_t)p * NA + aa) * QQ + k] = qd;
        }
    }
}

// ================= Stage 2: backprojection =================
// Block: 8 images (4 pairs) x 8 image rows x 128 cols; 256 threads.
// Per (pixel, angle): one k0/w shared by 8 images; per image-pair one LDS.64.
__device__ __forceinline__ void cp_async16(void* dst, const void* src) {
    unsigned s = (unsigned)__cvta_generic_to_shared(dst);
    asm volatile("cp.async.cg.shared.global [%0], [%1], 16;" :: "r"(s), "l"(src));
}

__global__ __launch_bounds__(256) void backproj_kernel(const uint2* __restrict__ Q,
                                                       float* __restrict__ out) {
    __shared__ uint2  qb[2][4 * QQ];   // double-buffered: 4 pair-rows of quads
    __shared__ float2 csn[NA];

    const int t   = threadIdx.x;
    const int seg = blockIdx.x;        // 0..15 -> image rows [seg*8, seg*8+8)
    const int bg  = blockIdx.y;        // 0..31 -> images [bg*8, bg*8+8), pairs bg*4..

    for (int idx = t; idx < NA; idx += 256) {
        double th = ((double)idx + 0.5) * (PI_D / (double)NA);
        double s, c;
        sincos(th, &s, &c);
        csn[idx] = make_float2((float)(c * INVDC_D), (float)(s * INVDC_D));
    }

    const int j  = t & 127;
    const int i0 = seg * 8 + (t >> 7) * 4;
    const float Yj = -20.0f + ((float)j  + 0.5f) * 0.3125f;
    const float Xi = -20.0f + ((float)i0 + 0.5f) * 0.3125f;

    const uint2* Qb = Q + (size_t)(bg * 4) * NA * QQ;

    // prologue: prefetch angle 0 (4 pair-rows, 92 x 16B chunks each)
    for (int u = t; u < 4 * 92; u += 256) {
        int pp = u / 92, c = u - pp * 92;
        cp_async16(&qb[0][pp * QQ + 2 * c], &Qb[((size_t)pp * NA) * QQ + 2 * c]);
    }
    asm volatile("cp.async.commit_group;");

    float acc[8][4];
    #pragma unroll
    for (int v = 0; v < 8; v++)
        #pragma unroll
        for (int ii = 0; ii < 4; ii++) acc[v][ii] = 0.0f;

    asm volatile("cp.async.wait_group 0;");
    __syncthreads();

    int cur = 0;
    for (int a = 0; a < NA; a++) {
        const int nxt = cur ^ 1;
        if (a + 1 < NA) {
            for (int u = t; u < 4 * 92; u += 256) {
                int pp = u / 92, c = u - pp * 92;
                cp_async16(&qb[nxt][pp * QQ + 2 * c],
                           &Qb[((size_t)pp * NA + (a + 1)) * QQ + 2 * c]);
            }
        }
        asm volatile("cp.async.commit_group;");

        const float2 cs  = csn[a];
        const float  kf0 = fmaf(cs.x, Xi, fmaf(cs.y, Yj, 91.0f)); // RHO/DC-0.5 == 91
        const float  dk  = cs.x * 0.3125f;
        const uint2* qc  = qb[cur];

        #pragma unroll
        for (int ii = 0; ii < 4; ii++) {
            float kf = fmaf((float)ii, dk, kf0);
            kf = fminf(fmaxf(kf, 0.0f), 182.0f);
            int k0 = (int)kf;
            k0 = min(k0, 181);
            float w  = kf - (float)k0;
            float wm = 1.0f - w;
            #pragma unroll
            for (int pp = 0; pp < 4; pp++) {
                uint2 qd = qc[pp * QQ + k0];                       // LDS.64
                float2 f0 = __half22float2(*(const __half2*)&qd.x); // (g0_b0, g0_b1)
                float2 f1 = __half22float2(*(const __half2*)&qd.y); // (g1_b0, g1_b1)
                float a0v = acc[2 * pp][ii];
                float a1v = acc[2 * pp + 1][ii];
                a0v = fmaf(wm, f0.x, a0v);
                a0v = fmaf(w,  f1.x, a0v);
                a1v = fmaf(wm, f0.y, a1v);
                a1v = fmaf(w,  f1.y, a1v);
                acc[2 * pp][ii]     = a0v;
                acc[2 * pp + 1][ii] = a1v;
            }
        }

        if (a + 1 < NA) {
            asm volatile("cp.async.wait_group 0;");
            __syncthreads();
            cur = nxt;
        }
    }

    const float sc = (float)(PI_D / (double)NA);
    #pragma unroll
    for (int pp = 0; pp < 4; pp++) {
        #pragma unroll
        for (int vb = 0; vb < 2; vb++) {
            int img = bg * 8 + pp * 2 + vb;
            #pragma unroll
            for (int ii = 0; ii < 4; ii++) {
                out[(size_t)img * (NI * NI) + (size_t)(i0 + ii) * NI + j] =
                    acc[2 * pp + vb][ii] * sc;
            }
        }
    }
}

// ================= launch =================
extern "C" void kernel_launch(void* const* d_in, const int* in_sizes, int n_in,
                              void* d_out, int out_size) {
    (void)in_sizes; (void)n_in; (void)out_size;
    const float* x = (const float*)d_in[0];
    float* out = (float*)d_out;

    uint2* qptr = nullptr;
    cudaGetSymbolAddress((void**)&qptr, g_q);

    filter_kernel<<<dim3(143, 128), 192>>>(x, qptr);
    backproj_kernel<<<dim3(16, 32), 256>>>(qptr, out);
}

// round 4
// speedup vs baseline: 1.3735x; 1.1314x over previous
#include <cuda_runtime.h>
#include <cuda_fp16.h>
#include <math.h>

// ---------------- problem constants ----------------
constexpr int NB = 256;    // batch
constexpr int NA = 285;    // angles
constexpr int ND = 183;    // detectors
constexpr int NI = 128;    // image N
constexpr int QQ = 184;    // quads per row (stride)

constexpr double RHO_D    = 1.4142135623730951 * 20.0;
constexpr double DC_D     = 2.0 * RHO_D / 183.0;
constexpr double INVDC_D  = 1.0 / DC_D;
constexpr double H0_D     = 1.0 / (4.0 * DC_D * DC_D);
constexpr double SCALEQ_D = 12.0 * DC_D;
constexpr double PI_D     = 3.141592653589793;

// filtered sinogram, fp16 4-image-interleaved quads:
// Q[group][a][k] = halfs (q_b0[k],q_b1[k],q_b2[k],q_b3[k], q_b0[k+1],...,q_b3[k+1])  (16B)
// 64 groups * 285 * 184 * 16B = 53.7 MB static scratch
__device__ uint4 g_q[(size_t)(NB / 4) * NA * QQ];

// ================= Stage 1: ramp filter (banded conv) =================
// Block: 4 images (one group) x 1 angle; 192 threads = 4 rows x 48.
__global__ __launch_bounds__(192) void filter_kernel(const float* __restrict__ x,
                                                     uint4* __restrict__ Q) {
    __shared__ float   xs[4 * 200];      // 4 rows, zero-padded, stride 200
    __shared__ float   Godd[200];        // g(2i-181), zero beyond |o|>181
    __shared__ float2  G2[192];          // (Godd[i], Godd[i+1])
    __shared__ __half  st[184 * 4];      // [n][r]  (r = image-in-group)

    const int t  = threadIdx.x;
    const int a  = blockIdx.x;           // angle
    const int g  = blockIdx.y;           // image group (4 images)
    const int b0 = 4 * g;

    if (t < 200) {
        int o = 2 * t - 181;
        float v = 0.0f;
        if (o >= -181 && o <= 181) {
            double d = PI_D * (double)o * DC_D;
            v = (float)(-1.0 / (d * d));
        }
        Godd[t] = v;
    }

    #pragma unroll
    for (int r = 0; r < 4; r++) {
        const float* xr = x + ((size_t)(b0 + r) * NA + a) * ND;
        xs[r * 200 + t] = (t < ND) ? xr[t] : 0.0f;
        if (t < 8) xs[r * 200 + 192 + t] = 0.0f;
    }
    __syncthreads();
    if (t < 192) G2[t] = make_float2(Godd[t], Godd[t + 1]);
    __syncthreads();

    const int r  = t & 3;
    const int n0 = (t >> 2) * 4;                  // 0..188
    const float*  xr = xs + r * 200;
    const float2* g2 = G2   + (n0 >> 1) + 90;
    const float*  gs = Godd + (n0 >> 1) + 92;

    float c0 = 0.f, c1 = 0.f, c2 = 0.f, c3 = 0.f;

    #pragma unroll 7
    for (int s = 0; s < 91; s++) {
        float2 xv = *(const float2*)(xr + 2 * s);   // (x[2s], x[2s+1])
        float2 ge = g2[-s];
        float  g3 = gs[-s];
        c0 = fmaf(xv.y, ge.x, c0);
        c2 = fmaf(xv.y, ge.y, c2);
        c1 = fmaf(xv.x, ge.y, c1);
        c3 = fmaf(xv.x, g3,   c3);
    }
    { // epilogue m = 182 (even) -> odd outputs only
        float  xe = xr[182];
        float2 gg = G2[n0 >> 1];
        c1 = fmaf(xe, gg.x, c1);
        c3 = fmaf(xe, gg.y, c3);
    }
    { // center tap
        const float h0 = (float)H0_D;
        c0 = fmaf(h0, xr[n0 + 0], c0);
        c1 = fmaf(h0, xr[n0 + 1], c1);
        c2 = fmaf(h0, xr[n0 + 2], c2);
        c3 = fmaf(h0, xr[n0 + 3], c3);
    }

    const float sc = (float)SCALEQ_D;
    if (n0 + 3 < QQ) {                    // n0 <= 180 -> writes n up to 183
        int base = n0 * 4 + r;
        st[base + 0]  = __float2half_rn(c0 * sc);
        st[base + 4]  = __float2half_rn(c1 * sc);
        st[base + 8]  = __float2half_rn(c2 * sc);
        st[base + 12] = __float2half_rn(c3 * sc);
    }
    __syncthreads();

    // quad k = halves [k*4 .. k*4+3] ++ [(k+1)*4 .. +3]
    if (t < ND) {
        const uint2* sp = (const uint2*)st;
        uint2 lo = sp[t];
        uint2 hi = sp[t + 1];
        Q[((size_t)g * NA + a) * QQ + t] = make_uint4(lo.x, lo.y, hi.x, hi.y);
    }
}

// ================= Stage 2: backprojection =================
// Block: 8 images (2 quad-groups) x 8 image rows x 128 cols; 256 threads.
// Per (pixel, angle): one k0/w shared by 8 images; per 4 images one LDS.128
// + HFMA2 fp16 lerp + f32 accumulate.
__device__ __forceinline__ void cp_async16(unsigned dst, const void* src) {
    asm volatile("cp.async.cg.shared.global [%0], [%1], 16;" :: "r"(dst), "l"(src));
}

__global__ __launch_bounds__(256) void backproj_kernel(const uint4* __restrict__ Q,
                                                       float* __restrict__ out) {
    __shared__ uint4  qb[2][2 * QQ];   // double-buffered: 2 group-rows of quads
    __shared__ float2 csn[NA];

    const int t   = threadIdx.x;
    const int seg = blockIdx.x;        // 0..15 -> image rows [seg*8, seg*8+8)
    const int bg  = blockIdx.y;        // 0..31 -> images [bg*8, bg*8+8)

    for (int idx = t; idx < NA; idx += 256) {
        double th = ((double)idx + 0.5) * (PI_D / (double)NA);
        double s, c;
        sincos(th, &s, &c);
        csn[idx] = make_float2((float)(c * INVDC_D), (float)(s * INVDC_D));
    }

    const int j  = t & 127;
    const int i0 = seg * 8 + (t >> 7) * 4;
    const float Yj = -20.0f + ((float)j  + 0.5f) * 0.3125f;
    const float Xi = -20.0f + ((float)i0 + 0.5f) * 0.3125f;

    const uint4* Qb = Q + (size_t)(bg * 2) * NA * QQ;

    // hoisted prefetch-chunk decomposition (2*QQ = 368 chunks, 256 threads)
    const int u0 = t;
    const int pp0 = u0 / QQ, c0i = u0 - pp0 * QQ;
    const int u1 = t + 256;
    const bool has1 = (u1 < 2 * QQ);
    const int pp1 = has1 ? (u1 / QQ) : 0, c1i = has1 ? (u1 - (u1 / QQ) * QQ) : 0;

    const uint4* src0 = Qb + ((size_t)pp0 * NA) * QQ + c0i;
    const uint4* src1 = Qb + ((size_t)pp1 * NA) * QQ + c1i;
    const unsigned sb = (unsigned)__cvta_generic_to_shared(&qb[0][0]);
    const unsigned d0a = sb + (pp0 * QQ + c0i) * 16;
    const unsigned d1a = sb + (pp1 * QQ + c1i) * 16;
    const unsigned BUFB = 2 * QQ * 16;

    // prologue: angle 0 into buffer 0
    cp_async16(d0a, src0);
    if (has1) cp_async16(d1a, src1);
    asm volatile("cp.async.commit_group;");
    src0 += QQ; src1 += QQ;

    float acc[8][4];
    #pragma unroll
    for (int v = 0; v < 8; v++)
        #pragma unroll
        for (int ii = 0; ii < 4; ii++) acc[v][ii] = 0.0f;

    asm volatile("cp.async.wait_group 0;");
    __syncthreads();

    int cur = 0;
    for (int a = 0; a < NA; a++) {
        if (a + 1 < NA) {
            unsigned off = (cur ^ 1) ? BUFB : 0u;
            cp_async16(d0a + off, src0);
            if (has1) cp_async16(d1a + off, src1);
            src0 += QQ; src1 += QQ;
        }
        asm volatile("cp.async.commit_group;");

        const float2 cs  = csn[a];
        const float  kf0 = fmaf(cs.x, Xi, fmaf(cs.y, Yj, 91.0f)); // RHO/DC-0.5 == 91
        const float  dk  = cs.x * 0.3125f;
        const uint4* qc  = qb[cur];

        #pragma unroll
        for (int ii = 0; ii < 4; ii++) {
            float kf = fmaf((float)ii, dk, kf0);
            int   k0 = (int)kf;                 // kf in [0.2, 181.8]: no clamps needed
            float w  = kf - (float)k0;
            __half2 wv  = __floats2half2_rn(1.0f - w, w);
            __half2 wm2 = __half2half2(__low2half(wv));
            __half2 w2  = __half2half2(__high2half(wv));
            #pragma unroll
            for (int gq = 0; gq < 2; gq++) {
                uint4 qd = qc[gq * QQ + k0];                    // LDS.128
                __half2 g0lo = *(const __half2*)&qd.x;          // (b0,b1) @ k0
                __half2 g0hi = *(const __half2*)&qd.y;          // (b2,b3) @ k0
                __half2 g1lo = *(const __half2*)&qd.z;          // (b0,b1) @ k0+1
                __half2 g1hi = *(const __half2*)&qd.w;          // (b2,b3) @ k0+1
                __half2 tlo = __hfma2(w2, g1lo, __hmul2(wm2, g0lo));
                __half2 thi = __hfma2(w2, g1hi, __hmul2(wm2, g0hi));
                acc[gq * 4 + 0][ii] += __low2float(tlo);
                acc[gq * 4 + 1][ii] += __high2float(tlo);
                acc[gq * 4 + 2][ii] += __low2float(thi);
                acc[gq * 4 + 3][ii] += __high2float(thi);
            }
        }

        if (a + 1 < NA) {
            asm volatile("cp.async.wait_group 0;");
            __syncthreads();
            cur ^= 1;
        }
    }

    const float sc = (float)(PI_D / (double)NA);
    #pragma unroll
    for (int gq = 0; gq < 2; gq++) {
        #pragma unroll
        for (int rr = 0; rr < 4; rr++) {
            int img = bg * 8 + gq * 4 + rr;
            #pragma unroll
            for (int ii = 0; ii < 4; ii++) {
                out[(size_t)img * (NI * NI) + (size_t)(i0 + ii) * NI + j] =
                    acc[gq * 4 + rr][ii] * sc;
            }
        }
    }
}

// ================= launch =================
extern "C" void kernel_launch(void* const* d_in, const int* in_sizes, int n_in,
                              void* d_out, int out_size) {
    (void)in_sizes; (void)n_in; (void)out_size;
    const float* x = (const float*)d_in[0];
    float* out = (float*)d_out;

    uint4* qptr = nullptr;
    cudaGetSymbolAddress((void**)&qptr, g_q);

    filter_kernel<<<dim3(NA, NB / 4), 192>>>(x, qptr);
    backproj_kernel<<<dim3(16, 32), 256>>>(qptr, out);
}

// round 5
// speedup vs baseline: 1.5383x; 1.1200x over previous
#include <cuda_runtime.h>
#include <cuda_fp16.h>
#include <math.h>

// ---------------- problem constants ----------------
constexpr int NB = 256;    // batch
constexpr int NA = 285;    // angles
constexpr int ND = 183;    // detectors
constexpr int NI = 128;    // image N
constexpr int QQ = 184;    // quads per row (stride)

constexpr double RHO_D    = 1.4142135623730951 * 20.0;
constexpr double DC_D     = 2.0 * RHO_D / 183.0;
constexpr double INVDC_D  = 1.0 / DC_D;
constexpr double H0_D     = 1.0 / (4.0 * DC_D * DC_D);
constexpr double SCALEQ_D = 12.0 * DC_D;
constexpr double PI_D     = 3.141592653589793;

// filtered sinogram, fp16 4-image-interleaved quads:
// Q[group][a][k] = halfs (q_b0[k],q_b1[k],q_b2[k],q_b3[k], q_b0[k+1],...)  (16B)
__device__ uint4 g_q[(size_t)(NB / 4) * NA * QQ];

// ================= Stage 1: ramp filter (banded conv) =================
__global__ __launch_bounds__(192) void filter_kernel(const float* __restrict__ x,
                                                     uint4* __restrict__ Q) {
    __shared__ float   xs[4 * 200];
    __shared__ float   Godd[200];
    __shared__ float2  G2[192];
    __shared__ __half  st[184 * 4];

    const int t  = threadIdx.x;
    const int a  = blockIdx.x;
    const int g  = blockIdx.y;
    const int b0 = 4 * g;

    if (t < 200) {
        int o = 2 * t - 181;
        float v = 0.0f;
        if (o >= -181 && o <= 181) {
            double d = PI_D * (double)o * DC_D;
            v = (float)(-1.0 / (d * d));
        }
        Godd[t] = v;
    }

    #pragma unroll
    for (int r = 0; r < 4; r++) {
        const float* xr = x + ((size_t)(b0 + r) * NA + a) * ND;
        xs[r * 200 + t] = (t < ND) ? xr[t] : 0.0f;
        if (t < 8) xs[r * 200 + 192 + t] = 0.0f;
    }
    __syncthreads();
    if (t < 192) G2[t] = make_float2(Godd[t], Godd[t + 1]);
    __syncthreads();

    const int r  = t & 3;
    const int n0 = (t >> 2) * 4;
    const float*  xr = xs + r * 200;
    const float2* g2 = G2   + (n0 >> 1) + 90;
    const float*  gs = Godd + (n0 >> 1) + 92;

    float c0 = 0.f, c1 = 0.f, c2 = 0.f, c3 = 0.f;

    #pragma unroll 7
    for (int s = 0; s < 91; s++) {
        float2 xv = *(const float2*)(xr + 2 * s);
        float2 ge = g2[-s];
        float  g3 = gs[-s];
        c0 = fmaf(xv.y, ge.x, c0);
        c2 = fmaf(xv.y, ge.y, c2);
        c1 = fmaf(xv.x, ge.y, c1);
        c3 = fmaf(xv.x, g3,   c3);
    }
    {
        float  xe = xr[182];
        float2 gg = G2[n0 >> 1];
        c1 = fmaf(xe, gg.x, c1);
        c3 = fmaf(xe, gg.y, c3);
    }
    {
        const float h0 = (float)H0_D;
        c0 = fmaf(h0, xr[n0 + 0], c0);
        c1 = fmaf(h0, xr[n0 + 1], c1);
        c2 = fmaf(h0, xr[n0 + 2], c2);
        c3 = fmaf(h0, xr[n0 + 3], c3);
    }

    const float sc = (float)SCALEQ_D;
    if (n0 + 3 < QQ) {
        int base = n0 * 4 + r;
        st[base + 0]  = __float2half_rn(c0 * sc);
        st[base + 4]  = __float2half_rn(c1 * sc);
        st[base + 8]  = __float2half_rn(c2 * sc);
        st[base + 12] = __float2half_rn(c3 * sc);
    }
    __syncthreads();

    if (t < ND) {
        const uint2* sp = (const uint2*)st;
        uint2 lo = sp[t];
        uint2 hi = sp[t + 1];
        Q[((size_t)g * NA + a) * QQ + t] = make_uint4(lo.x, lo.y, hi.x, hi.y);
    }
}

// ================= Stage 2: backprojection =================
// 3-deep pipeline of 2-angle stages; 8 images x 8 rows x 128 cols per block.
constexpr int APS    = 2;                 // angles per stage
constexpr int STAGES = (NA + APS - 1) / APS;   // 143
constexpr int CHUNK  = APS * 2 * QQ;      // uint4 per stage buffer = 736
constexpr unsigned CHUNKB = CHUNK * 16;

__device__ __forceinline__ void cp_async16(unsigned dst, const void* src) {
    asm volatile("cp.async.cg.shared.global [%0], [%1], 16;" :: "r"(dst), "l"(src));
}

__global__ __launch_bounds__(256) void backproj_kernel(const uint4* __restrict__ Q,
                                                       float* __restrict__ out) {
    __shared__ uint4  qb[3][CHUNK];
    __shared__ float2 csn[NA];

    const int t   = threadIdx.x;
    const int seg = blockIdx.x;
    const int bg  = blockIdx.y;

    for (int idx = t; idx < NA; idx += 256) {
        double th = ((double)idx + 0.5) * (PI_D / (double)NA);
        double s, c;
        sincos(th, &s, &c);
        csn[idx] = make_float2((float)(c * INVDC_D), (float)(s * INVDC_D));
    }

    const int j  = t & 127;
    const int i0 = seg * 8 + (t >> 7) * 4;
    const float Yj = -20.0f + ((float)j  + 0.5f) * 0.3125f;
    const float Xi = -20.0f + ((float)i0 + 0.5f) * 0.3125f;

    const uint4* Qb = Q + (size_t)(bg * 2) * NA * QQ;

    // ---- hoisted 3-slot chunk decomposition: u = t, t+256, t+512 over [0,736)
    // slot0: u=t         -> ai=0, pp=t/184, c=t%184
    // slot1: u=t+256     -> ai = (u>=368), v=u-ai*368, pp=v/184, c=v%184
    // slot2: u=t+512     -> ai=1, v=u-368, pp=v/184, c=v%184 (valid t<224)
    const int pp0 = t / 184,               c0i = t - pp0 * 184;
    const int u1  = t + 256;
    const int ai1 = (u1 >= 368) ? 1 : 0;
    const int v1  = u1 - ai1 * 368;
    const int pp1 = v1 / 184,              c1i = v1 - pp1 * 184;
    const int u2  = t + 512;
    const bool has2 = (u2 < CHUNK);
    const int v2  = u2 - 368;
    const int pp2 = has2 ? (v2 / 184) : 0, c2i = has2 ? (v2 - (v2 / 184) * 184) : 0;

    const uint4* src0 = Qb + ((size_t)pp0 * NA + 0  ) * QQ + c0i;
    const uint4* src1 = Qb + ((size_t)pp1 * NA + ai1) * QQ + c1i;
    const uint4* src2 = Qb + ((size_t)pp2 * NA + 1  ) * QQ + c2i;

    const unsigned sb = (unsigned)__cvta_generic_to_shared(&qb[0][0]);
    const unsigned d0 = sb + (unsigned)(((0  * 2 + pp0) * QQ + c0i) * 16);
    const unsigned d1 = sb + (unsigned)(((ai1 * 2 + pp1) * QQ + c1i) * 16);
    const unsigned d2 = sb + (unsigned)(((1  * 2 + pp2) * QQ + c2i) * 16);

    // ---- prologue: prefetch stages 0,1,2 (all angles valid: max angle 5)
    #pragma unroll
    for (int s = 0; s < 3; s++) {
        unsigned off = s * CHUNKB;
        cp_async16(d0 + off, src0);
        cp_async16(d1 + off, src1);
        if (has2) cp_async16(d2 + off, src2);
        asm volatile("cp.async.commit_group;");
        src0 += APS * QQ; src1 += APS * QQ; src2 += APS * QQ;
    }

    float acc[8][4];
    #pragma unroll
    for (int v = 0; v < 8; v++)
        #pragma unroll
        for (int ii = 0; ii < 4; ii++) acc[v][ii] = 0.0f;

    int cur = 0;
    for (int stg = 0; stg < STAGES; stg++) {
        asm volatile("cp.async.wait_group 2;");
        __syncthreads();

        const int a0 = 2 * stg;
        const uint4* qs = qb[cur];

        #pragma unroll
        for (int ai = 0; ai < APS; ai++) {
            if (ai == 1 && a0 + 1 >= NA) break;   // only stage 142
            const float2 cs  = csn[a0 + ai];
            const float  kf0 = fmaf(cs.x, Xi, fmaf(cs.y, Yj, 91.0f));
            const float  dk  = cs.x * 0.3125f;
            const uint4* qc  = qs + ai * (2 * QQ);

            #pragma unroll
            for (int ii = 0; ii < 4; ii++) {
                float kf = fmaf((float)ii, dk, kf0);
                int   k0 = (int)kf;                 // kf in [0.2,181.8]
                float w  = kf - (float)k0;
                __half2 wv  = __floats2half2_rn(1.0f - w, w);
                __half2 wm2 = __half2half2(__low2half(wv));
                __half2 w2  = __half2half2(__high2half(wv));
                #pragma unroll
                for (int gq = 0; gq < 2; gq++) {
                    uint4 qd = qc[gq * QQ + k0];                   // LDS.128
                    __half2 g0lo = *(const __half2*)&qd.x;
                    __half2 g0hi = *(const __half2*)&qd.y;
                    __half2 g1lo = *(const __half2*)&qd.z;
                    __half2 g1hi = *(const __half2*)&qd.w;
                    __half2 tlo = __hfma2(w2, g1lo, __hmul2(wm2, g0lo));
                    __half2 thi = __hfma2(w2, g1hi, __hmul2(wm2, g0hi));
                    acc[gq * 4 + 0][ii] += __low2float(tlo);
                    acc[gq * 4 + 1][ii] += __high2float(tlo);
                    acc[gq * 4 + 2][ii] += __low2float(thi);
                    acc[gq * 4 + 3][ii] += __high2float(thi);
                }
            }
        }

        __syncthreads();   // all warps done reading qb[cur]

        // prefetch stage stg+3 into the freed buffer; always commit (invariant)
        const int stp = stg + 3;
        if (stp < STAGES) {
            const unsigned off = cur * CHUNKB;
            const bool full = (2 * stp + 1 < NA);     // false only for stage 142
            cp_async16(d0 + off, src0);
            if (full || ai1 == 0) cp_async16(d1 + off, src1);
            if (has2 && full)     cp_async16(d2 + off, src2);
            src0 += APS * QQ; src1 += APS * QQ; src2 += APS * QQ;
        }
        asm volatile("cp.async.commit_group;");

        cur = (cur == 2) ? 0 : cur + 1;
    }

    const float sc = (float)(PI_D / (double)NA);
    #pragma unroll
    for (int gq = 0; gq < 2; gq++) {
        #pragma unroll
        for (int rr = 0; rr < 4; rr++) {
            int img = bg * 8 + gq * 4 + rr;
            #pragma unroll
            for (int ii = 0; ii < 4; ii++) {
                out[(size_t)img * (NI * NI) + (size_t)(i0 + ii) * NI + j] =
                    acc[gq * 4 + rr][ii] * sc;
            }
        }
    }
}

// ================= launch =================
extern "C" void kernel_launch(void* const* d_in, const int* in_sizes, int n_in,
                              void* d_out, int out_size) {
    (void)in_sizes; (void)n_in; (void)out_size;
    const float* x = (const float*)d_in[0];
    float* out = (float*)d_out;

    uint4* qptr = nullptr;
    cudaGetSymbolAddress((void**)&qptr, g_q);

    filter_kernel<<<dim3(NA, NB / 4), 192>>>(x, qptr);
    backproj_kernel<<<dim3(16, 32), 256>>>(qptr, out);
}

// round 7
// speedup vs baseline: 1.8593x; 1.2087x over previous
#include <cuda_runtime.h>
#include <cuda_fp16.h>
#include <math.h>

// ---------------- problem constants ----------------
constexpr int NB = 256;    // batch
constexpr int NA = 285;    // angles
constexpr int ND = 183;    // detectors
constexpr int NI = 128;    // image N
constexpr int QQ = 184;    // quads per row (stride)

constexpr double RHO_D    = 1.4142135623730951 * 20.0;
constexpr double DC_D     = 2.0 * RHO_D / 183.0;
constexpr double INVDC_D  = 1.0 / DC_D;
constexpr double H0_D     = 1.0 / (4.0 * DC_D * DC_D);
constexpr double SCALEQ_D = 12.0 * DC_D;
constexpr double PI_D     = 3.141592653589793;

// filtered sinogram, fp16 4-image-interleaved (g0, delta) quads:
// Q[group][a][k] = halfs (g_b0[k],g_b1[k],g_b2[k],g_b3[k],
//                         (g[k+1]-g[k])_b0, ..., _b3)          (16B)
__device__ uint4 g_q[(size_t)(NB / 4) * NA * QQ];

// ================= Stage 1: ramp filter (banded conv) =================
// Block: 4 images (group) x 4 angles = 16 rows; 192 threads = 16 rows x 12.
// Each thread computes 16 consecutive outputs; the odd/even tap structure
// makes all 16 taps for step s a 9-float window of Godd -> unroll-4 shares
// one aligned 16-float window across 64 FMAs.
__global__ __launch_bounds__(192) void filter_kernel(const float* __restrict__ x,
                                                     uint4* __restrict__ Q) {
    __shared__ __align__(16) float xs[16 * 200];     // 16 rows, zero-padded
    __shared__ __align__(16) float Gs[224];          // Godd shifted +8, guarded
    __shared__ __align__(16) __half st[4 * 184 * 4]; // [va][n][im]

    const int t  = threadIdx.x;
    const int a0 = blockIdx.x * 4;                  // angle quad
    const int g  = blockIdx.y;                      // image group
    const int b0 = 4 * g;

    // Gs[j] = g(2*(j-8)-181) for j-8 in [0,181], else 0
    for (int jj = t; jj < 224; jj += 192) {
        int i = jj - 8;
        float v = 0.0f;
        if (i >= 0 && i <= 181) {
            int o = 2 * i - 181;                    // odd
            double d = PI_D * (double)o * DC_D;
            v = (float)(-1.0 / (d * d));
        }
        Gs[jj] = v;
    }

    // load 16 rows (angle-major: row = va*4 + im), zero-padded to 200
    for (int u = t; u < 16 * 200; u += 192) {
        int row = u / 200, col = u - row * 200;
        int va = row >> 2, im = row & 3;
        int aa = a0 + va;
        float v = 0.0f;
        if (col < ND && aa < NA)
            v = x[((size_t)(b0 + im) * NA + aa) * ND + col];
        xs[u] = v;
    }
    __syncthreads();

    const int r  = t / 12;           // row 0..15
    const int l  = t - r * 12;       // 0..11
    const int va = r >> 2, im = r & 3;
    const int n0 = 16 * l;
    const int E0 = 8 * l + 90;
    const float* xr = xs + r * 200;

    float acc[16];
    #pragma unroll
    for (int e = 0; e < 16; e++) acc[e] = 0.0f;

    // 23 unroll-4 blocks cover s = 0..91 (includes the even m=182 tap;
    // odd m=183 multiplies padded x[183]=0; Gs guard zeros absorb underrun)
    for (int s0 = 0; s0 < 92; s0 += 4) {
        float4 xq0 = *(const float4*)(xr + 2 * s0);      // x[2s0 .. 2s0+3]
        float4 xq1 = *(const float4*)(xr + 2 * s0 + 4);  // x[2s0+4 .. +7]
        const float4* Gv = (const float4*)(Gs + (E0 - s0 + 2)); // 4-aligned
        float4 g0v = Gv[0], g1v = Gv[1], g2v = Gv[2], g3v = Gv[3];
        float gg[16] = {g0v.x,g0v.y,g0v.z,g0v.w, g1v.x,g1v.y,g1v.z,g1v.w,
                        g2v.x,g2v.y,g2v.z,g2v.w, g3v.x,g3v.y,g3v.z,g3v.w};
        float xf[8] = {xq0.x,xq0.y,xq0.z,xq0.w, xq1.x,xq1.y,xq1.z,xq1.w};
        #pragma unroll
        for (int k = 0; k < 4; k++) {
            #pragma unroll
            for (int e = 0; e < 8; e++) {
                acc[2*e]   = fmaf(xf[2*k+1], gg[e + 6 - k], acc[2*e]);   // even n
                acc[2*e+1] = fmaf(xf[2*k],   gg[e + 7 - k], acc[2*e+1]); // odd n
            }
        }
    }
    { // center tap
        const float h0 = (float)H0_D;
        float4 c0 = *(const float4*)(xr + n0);
        float4 c1 = *(const float4*)(xr + n0 + 4);
        float4 c2 = *(const float4*)(xr + n0 + 8);
        float4 c3 = *(const float4*)(xr + n0 + 12);
        float cf[16] = {c0.x,c0.y,c0.z,c0.w, c1.x,c1.y,c1.z,c1.w,
                        c2.x,c2.y,c2.z,c2.w, c3.x,c3.y,c3.z,c3.w};
        #pragma unroll
        for (int e = 0; e < 16; e++) acc[e] = fmaf(h0, cf[e], acc[e]);
    }

    // stage as fp16: st[(va*184 + n)*4 + im]
    const float sc = (float)SCALEQ_D;
    #pragma unroll
    for (int e = 0; e < 16; e++) {
        int n = n0 + e;
        if (n < 184) st[(va * 184 + n) * 4 + im] = __float2half_rn(acc[e] * sc);
    }
    __syncthreads();

    // pack (g0, delta) quads
    for (int u = t; u < 4 * ND; u += 192) {
        int qa = u / ND, k = u - qa * ND;
        int aa = a0 + qa;
        if (aa < NA) {
            const uint2* sp = (const uint2*)(st + qa * 184 * 4);
            uint2 lo = sp[k];
            uint2 hi = sp[k + 1];
            __half2 d0 = __hsub2(*(const __half2*)&hi.x, *(const __half2*)&lo.x);
            __half2 d1 = __hsub2(*(const __half2*)&hi.y, *(const __half2*)&lo.y);
            Q[((size_t)g * NA + aa) * QQ + k] =
                make_uint4(lo.x, lo.y, *(const unsigned*)&d0, *(const unsigned*)&d1);
        }
    }
}

// ================= Stage 2: backprojection =================
// 3-deep pipeline of 2-angle stages; 8 images x 4 rows x 128 cols per block
// (1024 blocks -> balanced SM load). t = g0 + w*delta per 4 images (LDS.128).
constexpr int APS    = 2;
constexpr int STAGES = (NA + APS - 1) / APS;   // 143
constexpr int CHUNK  = APS * 2 * QQ;           // 736
constexpr unsigned CHUNKB = CHUNK * 16;

__device__ __forceinline__ void cp_async16(unsigned dst, const void* src) {
    asm volatile("cp.async.cg.shared.global [%0], [%1], 16;" :: "r"(dst), "l"(src));
}

__global__ __launch_bounds__(256) void backproj_kernel(const uint4* __restrict__ Q,
                                                       float* __restrict__ out) {
    __shared__ uint4  qb[3][CHUNK];
    __shared__ float2 csn[NA];

    const int t   = threadIdx.x;
    const int seg = blockIdx.x;        // 0..31 -> image rows [seg*4, seg*4+4)
    const int bg  = blockIdx.y;        // 0..31 -> images [bg*8, bg*8+8)

    for (int idx = t; idx < NA; idx += 256) {
        double th = ((double)idx + 0.5) * (PI_D / (double)NA);
        double s, c;
        sincos(th, &s, &c);
        csn[idx] = make_float2((float)(c * INVDC_D), (float)(s * INVDC_D));
    }

    const int j  = t & 127;
    const int i0 = seg * 4 + (t >> 7) * 2;
    const float Yj = -20.0f + ((float)j  + 0.5f) * 0.3125f;
    const float Xi = -20.0f + ((float)i0 + 0.5f) * 0.3125f;

    const uint4* Qb = Q + (size_t)(bg * 2) * NA * QQ;

    // hoisted 3-slot chunk decomposition over [0, 736)
    const int pp0 = t / 184,               c0i = t - pp0 * 184;
    const int u1  = t + 256;
    const int ai1 = (u1 >= 368) ? 1 : 0;
    const int v1  = u1 - ai1 * 368;
    const int pp1 = v1 / 184,              c1i = v1 - pp1 * 184;
    const int u2  = t + 512;
    const bool has2 = (u2 < CHUNK);
    const int v2  = u2 - 368;
    const int pp2 = has2 ? (v2 / 184) : 0, c2i = has2 ? (v2 - (v2 / 184) * 184) : 0;

    const uint4* src0 = Qb + ((size_t)pp0 * NA + 0  ) * QQ + c0i;
    const uint4* src1 = Qb + ((size_t)pp1 * NA + ai1) * QQ + c1i;
    const uint4* src2 = Qb + ((size_t)pp2 * NA + 1  ) * QQ + c2i;

    const unsigned sb = (unsigned)__cvta_generic_to_shared(&qb[0][0]);
    const unsigned d0 = sb + (unsigned)(((0  * 2 + pp0) * QQ + c0i) * 16);
    const unsigned d1 = sb + (unsigned)(((ai1 * 2 + pp1) * QQ + c1i) * 16);
    const unsigned d2 = sb + (unsigned)(((1  * 2 + pp2) * QQ + c2i) * 16);

    // prologue: prefetch stages 0..2
    #pragma unroll
    for (int s = 0; s < 3; s++) {
        unsigned off = s * CHUNKB;
        cp_async16(d0 + off, src0);
        cp_async16(d1 + off, src1);
        if (has2) cp_async16(d2 + off, src2);
        asm volatile("cp.async.commit_group;");
        src0 += APS * QQ; src1 += APS * QQ; src2 += APS * QQ;
    }

    float acc[8][2];
    #pragma unroll
    for (int v = 0; v < 8; v++) { acc[v][0] = 0.0f; acc[v][1] = 0.0f; }

    int cur = 0;
    for (int stg = 0; stg < STAGES; stg++) {
        asm volatile("cp.async.wait_group 2;");
        __syncthreads();

        const int a0 = 2 * stg;
        const uint4* qs = qb[cur];

        #pragma unroll
        for (int ai = 0; ai < APS; ai++) {
            if (ai == 1 && a0 + 1 >= NA) break;   // only last stage
            const float2 cs  = csn[a0 + ai];
            const float  kf0 = fmaf(cs.x, Xi, fmaf(cs.y, Yj, 91.0f));
            const float  dk  = cs.x * 0.3125f;
            const uint4* qc  = qs + ai * (2 * QQ);

            #pragma unroll
            for (int ii = 0; ii < 2; ii++) {
                float kf = fmaf((float)ii, dk, kf0);
                int   k0 = (int)kf;                 // kf in [0.2, 181.8]
                float w  = kf - (float)k0;
                __half2 w2 = __floats2half2_rn(w, w);
                #pragma unroll
                for (int gq = 0; gq < 2; gq++) {
                    uint4 qd = qc[gq * QQ + k0];                 // LDS.128
                    __half2 g0lo = *(const __half2*)&qd.x;       // (b0,b1)
                    __half2 g0hi = *(const __half2*)&qd.y;       // (b2,b3)
                    __half2 dlo  = *(const __half2*)&qd.z;
                    __half2 dhi  = *(const __half2*)&qd.w;
                    __half2 tlo = __hfma2(w2, dlo, g0lo);
                    __half2 thi = __hfma2(w2, dhi, g0hi);
                    acc[gq * 4 + 0][ii] += __low2float(tlo);
                    acc[gq * 4 + 1][ii] += __high2float(tlo);
                    acc[gq * 4 + 2][ii] += __low2float(thi);
                    acc[gq * 4 + 3][ii] += __high2float(thi);
                }
            }
        }

        __syncthreads();

        const int stp = stg + 3;
        if (stp < STAGES) {
            const unsigned off = cur * CHUNKB;
            const bool full = (2 * stp + 1 < NA);
            cp_async16(d0 + off, src0);
            if (full || ai1 == 0) cp_async16(d1 + off, src1);
            if (has2 && full)     cp_async16(d2 + off, src2);
            src0 += APS * QQ; src1 += APS * QQ; src2 += APS * QQ;
        }
        asm volatile("cp.async.commit_group;");

        cur = (cur == 2) ? 0 : cur + 1;
    }

    const float sc = (float)(PI_D / (double)NA);
    #pragma unroll
    for (int gq = 0; gq < 2; gq++) {
        #pragma unroll
        for (int rr = 0; rr < 4; rr++) {
            int img = bg * 8 + gq * 4 + rr;
            #pragma unroll
            for (int ii = 0; ii < 2; ii++) {
                out[(size_t)img * (NI * NI) + (size_t)(i0 + ii) * NI + j] =
                    acc[gq * 4 + rr][ii] * sc;
            }
        }
    }
}

// ================= launch =================
extern "C" void kernel_launch(void* const* d_in, const int* in_sizes, int n_in,
                              void* d_out, int out_size) {
    (void)in_sizes; (void)n_in; (void)out_size;
    const float* x = (const float*)d_in[0];
    float* out = (float*)d_out;

    uint4* qptr = nullptr;
    cudaGetSymbolAddress((void**)&qptr, g_q);

    filter_kernel<<<dim3((NA + 3) / 4, NB / 4), 192>>>(x, qptr);
    backproj_kernel<<<dim3(32, 32), 256>>>(qptr, out);
}